// round 12
// baseline (speedup 1.0000x reference)
#include <cuda_runtime.h>

// cumprod along dim 1 of a (4096, 8192) fp32 matrix.
// PERSISTENT-STATIC CTAs, register double-buffered across rows.
// Grid = 740 (5/SM x 148); CTA b processes rows b, b+740, ... (no atomics).
// Per row (R8 winner core): 8 warps, warp w owns floats [1024w,1024w+1024),
// lane L owns float4 L of each 128-float chunk (coalesced LDG/STG.128),
// local prefix folded pre-barrier, early butterfly segment totals, ONE
// barrier per row (parity-buffered wtot). While row r runs its scan+store
// (write) phase, row r+740's 8 LDG.128 are already in flight -> the DRAM
// read stream never goes idle.

#define ROW_LEN  8192
#define NROWS    4096
#define THREADS  256
#define NWARPS   8
#define CHUNKS   8
#define SEG_VEC  256
#define GRID     740

__device__ __forceinline__ void load_row(const float* __restrict__ x, int r,
                                         int segl, float4* buf) {
    const float4* __restrict__ xin =
        reinterpret_cast<const float4*>(x + (size_t)r * ROW_LEN);
    #pragma unroll
    for (int c = 0; c < CHUNKS; c++)
        buf[c] = __ldcs(&xin[segl + c * 32]);
}

// Process row r held in cur[]; prefetch row rn into nxt[] (if rn valid).
__device__ __forceinline__ void process_row(
    float* __restrict__ y, int r, int rn, int segl,
    float4* cur, float4* nxt, const float* __restrict__ x,
    float* wtot_p, int lane, int w) {

    // prefetch next row FIRST: 8 more LDG.128 in flight during this row's compute
    if (rn < NROWS)
        load_row(x, rn, segl, nxt);

    // fold local prefix in place, accumulate segment total
    float tp = 1.0f;
    #pragma unroll
    for (int c = 0; c < CHUNKS; c++) {
        float4 v = cur[c];
        v.y *= v.x;
        v.z *= v.y;
        v.w *= v.z;
        cur[c] = v;
        tp *= v.w;
    }
    #pragma unroll
    for (int o = 1; o < 32; o <<= 1)
        tp *= __shfl_xor_sync(0xffffffffu, tp, o);
    if (lane == 0) wtot_p[w] = tp;
    __syncthreads();                      // one barrier per row (parity slots)

    // cross-warp exclusive prefix
    float carry = 1.0f;
    #pragma unroll
    for (int ww = 0; ww < NWARPS - 1; ww++) {
        float wt = wtot_p[ww];
        if (ww < w) carry *= wt;
    }

    float4* __restrict__ yout =
        reinterpret_cast<float4*>(y + (size_t)r * ROW_LEN);

    // scan + scale + store
    #pragma unroll
    for (int c = 0; c < CHUNKS; c++) {
        float4 v = cur[c];
        float s = v.w;
        #pragma unroll
        for (int o = 1; o < 32; o <<= 1) {
            float tv = __shfl_up_sync(0xffffffffu, s, o);
            if (lane >= o) s *= tv;
        }
        float e   = __shfl_up_sync(0xffffffffu, s, 1);
        if (lane == 0) e = 1.0f;
        float tot = __shfl_sync(0xffffffffu, s, 31);

        const float ce = carry * e;
        v.x *= ce; v.y *= ce; v.z *= ce; v.w *= ce;
        __stcs(&yout[segl + c * 32], v);

        carry *= tot;
    }
}

__global__ void __launch_bounds__(THREADS, 3)
cumprod_dim1_kernel(const float* __restrict__ x, float* __restrict__ y) {
    __shared__ float wtot[2][NWARPS];

    const int t    = threadIdx.x;
    const int lane = t & 31;
    const int w    = t >> 5;
    const int segl = (t >> 5) * SEG_VEC + lane;

    float4 A[CHUNKS], B[CHUNKS];

    int r = blockIdx.x;
    load_row(x, r, segl, A);

    // unrolled-by-2 ping-pong; one __syncthreads per row, parity-safe wtot
    for (;;) {
        process_row(y, r, r + GRID, segl, A, B, x, wtot[0], lane, w);
        r += GRID;
        if (r >= NROWS) break;
        process_row(y, r, r + GRID, segl, B, A, x, wtot[1], lane, w);
        r += GRID;
        if (r >= NROWS) break;
    }
}

extern "C" void kernel_launch(void* const* d_in, const int* in_sizes, int n_in,
                              void* d_out, int out_size) {
    const float* x = (const float*)d_in[0];
    float* y = (float*)d_out;
    cumprod_dim1_kernel<<<GRID, THREADS>>>(x, y);
}